// round 13
// baseline (speedup 1.0000x reference)
#include <cuda_runtime.h>
#include <cstddef>
#include <cstdint>

#define NN  100000
#define DD  64
#define REX 8
#define RIM 4
#define EEX 2000000
#define EIM 1000000
#define NRE (NN * REX)               // 800000
#define NRI (NN * RIM)               // 400000
#define NBE ((NRE + 1023) / 1024)    // 782
#define NBI ((NRI + 1023) / 1024)    // 391

// ---------------- scratch (static device globals; no allocation) ----------------
__device__ int   g_cnt_ex[NRE];
__device__ int   g_cnt_im[NRI];
__device__ int   g_offs_ex[NRE];     // intra-block exclusive offsets
__device__ int   g_offs_im[NRI];
__device__ int   g_cur_ex[NRE];      // sort cursors (intra offsets)
__device__ int   g_cur_im[NRI];
__device__ int   g_bs_ex[1024];      // per-block sums
__device__ int   g_bs_im[1024];
__device__ int   g_bs2_ex[1024];     // exclusive block bases
__device__ int   g_bs2_im[1024];
__device__ int   g_ticket;
__device__ int   g_ssrc_ex[EEX];
__device__ int   g_ssrc_im[EIM];
__device__ float g_ex_x1[NN * DD];
__device__ float g_im_x1[NN * DD];
__device__ float g_t_ex[NN * DD];
__device__ float g_t_im[NN * DD];
__device__ float g_ex_sum[NN * DD];
__device__ float g_im_sum[NN * DD];

// ---------------- tf32 helpers ----------------
__device__ __forceinline__ unsigned f2tf(float x) {
    unsigned u;
    asm("cvt.rna.tf32.f32 %0, %1;" : "=r"(u) : "f"(x));
    return u;
}

__device__ __forceinline__ void mma8(float* c, const unsigned* a, unsigned b0, unsigned b1) {
    asm volatile("mma.sync.aligned.m16n8k8.row.col.f32.tf32.tf32.f32 "
                 "{%0,%1,%2,%3}, {%4,%5,%6,%7}, {%8,%9}, {%0,%1,%2,%3};"
                 : "+f"(c[0]), "+f"(c[1]), "+f"(c[2]), "+f"(c[3])
                 : "r"(a[0]), "r"(a[1]), "r"(a[2]), "r"(a[3]), "r"(b0), "r"(b1));
}

// ---------------- two-level segment offset ----------------
__device__ __forceinline__ int seg_off(const int* __restrict__ offs,
                                       const int* __restrict__ bs2,
                                       int key, int nkeys, int E) {
    if (key >= nkeys) return E;
    return bs2[key >> 10] + offs[key];
}

// ---------------- kernel 1: count per (dst, relation), both edge sets ----------------
__global__ void count_both(const int* __restrict__ dst_ex, const int* __restrict__ et_ex,
                           const int* __restrict__ dst_im, const int* __restrict__ et_im,
                           int* __restrict__ ce, int* __restrict__ ci) {
    int i = blockIdx.x * blockDim.x + threadIdx.x;
    if (i < EEX) {
        atomicAdd(&ce[dst_ex[i] * REX + et_ex[i]], 1);
    } else if (i < EEX + EIM) {
        int e = i - EEX;
        atomicAdd(&ci[dst_im[e] * RIM + et_im[e]], 1);
    }
}

// ---------------- kernel 2: fused scan (intra-block scan + last-block bs2 scan) -------
// Blocks [0,NBE) handle ex, rest im. Each block writes intra offsets to offs AND cur,
// plus its block sum. The LAST block (ticket) scans both bsum arrays into bs2.
__device__ void scan1024_cg(const int* __restrict__ in, int* __restrict__ out,
                            int n, int* s) {
    int t = threadIdx.x;
    int base = t * 4;
    int v0 = (base     < n) ? __ldcg(in + base)     : 0;
    int v1 = (base + 1 < n) ? __ldcg(in + base + 1) : 0;
    int v2 = (base + 2 < n) ? __ldcg(in + base + 2) : 0;
    int v3 = (base + 3 < n) ? __ldcg(in + base + 3) : 0;
    int tot = v0 + v1 + v2 + v3;
    s[t] = tot;
    __syncthreads();
    #pragma unroll
    for (int o = 1; o < 256; o <<= 1) {
        int x = (t >= o) ? s[t - o] : 0;
        __syncthreads();
        s[t] += x;
        __syncthreads();
    }
    int excl = s[t] - tot;
    if (base     < n) out[base]     = excl;
    if (base + 1 < n) out[base + 1] = excl + v0;
    if (base + 2 < n) out[base + 2] = excl + v0 + v1;
    if (base + 3 < n) out[base + 3] = excl + v0 + v1 + v2;
    __syncthreads();
}

__global__ void scan_fused(const int* __restrict__ in_ex, int* __restrict__ offs_ex,
                           int* __restrict__ cur_ex, int* __restrict__ bsum_ex,
                           int* __restrict__ bs2_ex,
                           const int* __restrict__ in_im, int* __restrict__ offs_im,
                           int* __restrict__ cur_im, int* __restrict__ bsum_im,
                           int* __restrict__ bs2_im,
                           int* __restrict__ ticket) {
    __shared__ int s[256];
    __shared__ int is_last;
    int b = blockIdx.x;
    const int* in; int* outo; int* outc; int* bsum; int idx; int n;
    if (b < NBE) { in = in_ex; outo = offs_ex; outc = cur_ex; bsum = bsum_ex; idx = b;       n = NRE; }
    else         { in = in_im; outo = offs_im; outc = cur_im; bsum = bsum_im; idx = b - NBE; n = NRI; }
    int t = threadIdx.x;
    int base = idx * 1024 + t * 4;
    int v0 = (base     < n) ? in[base]     : 0;
    int v1 = (base + 1 < n) ? in[base + 1] : 0;
    int v2 = (base + 2 < n) ? in[base + 2] : 0;
    int v3 = (base + 3 < n) ? in[base + 3] : 0;
    int tot = v0 + v1 + v2 + v3;
    s[t] = tot;
    __syncthreads();
    #pragma unroll
    for (int o = 1; o < 256; o <<= 1) {
        int x = (t >= o) ? s[t - o] : 0;
        __syncthreads();
        s[t] += x;
        __syncthreads();
    }
    int excl = s[t] - tot;
    if (base     < n) { outo[base]     = excl;                outc[base]     = excl; }
    if (base + 1 < n) { outo[base + 1] = excl + v0;           outc[base + 1] = excl + v0; }
    if (base + 2 < n) { outo[base + 2] = excl + v0 + v1;      outc[base + 2] = excl + v0 + v1; }
    if (base + 3 < n) { outo[base + 3] = excl + v0 + v1 + v2; outc[base + 3] = excl + v0 + v1 + v2; }
    if (t == 255) bsum[idx] = s[255];

    // ---- last-block: scan block sums into bs2 (both arrays) ----
    __threadfence();
    __syncthreads();
    if (t == 0) {
        int old = atomicAdd(ticket, 1);
        is_last = (old == (int)gridDim.x - 1);
    }
    __syncthreads();
    if (is_last) {
        scan1024_cg(bsum_ex, bs2_ex, NBE, s);
        scan1024_cg(bsum_im, bs2_im, NBI, s);
    }
}

// ---------------- kernel 3: counting sort (two-level position) ----------------
__global__ void sort_both(const int* __restrict__ src_ex, const int* __restrict__ dst_ex,
                          const int* __restrict__ et_ex,
                          const int* __restrict__ src_im, const int* __restrict__ dst_im,
                          const int* __restrict__ et_im,
                          int* __restrict__ cur_ex, const int* __restrict__ bs2_ex,
                          int* __restrict__ ssrc_ex,
                          int* __restrict__ cur_im, const int* __restrict__ bs2_im,
                          int* __restrict__ ssrc_im) {
    int i = blockIdx.x * blockDim.x + threadIdx.x;
    if (i < EEX) {
        int key = dst_ex[i] * REX + et_ex[i];
        int pos = bs2_ex[key >> 10] + atomicAdd(&cur_ex[key], 1);
        ssrc_ex[pos] = src_ex[i];
    } else if (i < EEX + EIM) {
        int e = i - EEX;
        int key = dst_im[e] * RIM + et_im[e];
        int pos = bs2_im[key >> 10] + atomicAdd(&cur_im[key], 1);
        ssrc_im[pos] = src_im[e];
    }
}

// ---------------- kernels 4,5: layer-1 aggregate (#4 = ex -> PROFILED) ---------------
__global__ void agg_l1(const float* __restrict__ W, const int* __restrict__ ssrc,
                       const int* __restrict__ offs, const int* __restrict__ bs2,
                       const float* __restrict__ root, const float* __restrict__ bias,
                       float* __restrict__ out, int R, int E) {
    int idx  = blockIdx.x * blockDim.x + threadIdx.x;
    int d    = idx >> 4;
    int lane = idx & 15;
    if (d >= NN) return;
    float4 b = reinterpret_cast<const float4*>(bias)[lane];
    float4 acc = reinterpret_cast<const float4*>(root)[(size_t)d * 16 + lane];
    acc.x += b.x; acc.y += b.y; acc.z += b.z; acc.w += b.w;
    int nk = NN * R;
    int beg = seg_off(offs, bs2, d * R, nk, E);
    for (int r = 0; r < R; r++) {
        int end = seg_off(offs, bs2, d * R + r + 1, nk, E);
        if (end > beg) {
            float4 s = make_float4(0.f, 0.f, 0.f, 0.f);
            for (int e = beg; e < end; e++) {
                int sv = ssrc[e];
                float4 v = reinterpret_cast<const float4*>(W)[((size_t)r * NN + sv) * 16 + lane];
                s.x += v.x; s.y += v.y; s.z += v.z; s.w += v.w;
            }
            float inv = 1.0f / (float)(end - beg);
            acc.x += s.x * inv; acc.y += s.y * inv; acc.z += s.z * inv; acc.w += s.w * inv;
        }
        beg = end;
    }
    reinterpret_cast<float4*>(out)[(size_t)d * 16 + lane] = acc;
}

// ---------------- ATTITU fusion (warp per node) ----------------
__global__ void attitu_kernel(const float* __restrict__ ex1, const float* __restrict__ im1,
                              const float* __restrict__ w11, const float* __restrict__ b11,
                              const float* __restrict__ w12, const float* __restrict__ b12,
                              const float* __restrict__ w21, const float* __restrict__ b21,
                              const float* __restrict__ w22, const float* __restrict__ b22,
                              float* __restrict__ t_ex, float* __restrict__ t_im, int nnodes) {
    int g    = blockIdx.x * blockDim.x + threadIdx.x;
    int node = g >> 5;
    int lane = g & 31;
    if (node >= nnodes) return;
    const float* e1 = ex1 + (size_t)node * DD;
    const float* e2 = im1 + (size_t)node * DD;
    float a0 = e1[lane], a1 = e1[lane + 32];
    float c0 = e2[lane], c1 = e2[lane + 32];
    float p11 = a0 * w11[lane] + a1 * w11[lane + 32];
    float p12 = c0 * w12[lane] + c1 * w12[lane + 32];
    float p21 = a0 * w21[lane] + a1 * w21[lane + 32];
    float p22 = c0 * w22[lane] + c1 * w22[lane + 32];
    #pragma unroll
    for (int o = 16; o > 0; o >>= 1) {
        p11 += __shfl_xor_sync(0xFFFFFFFF, p11, o);
        p12 += __shfl_xor_sync(0xFFFFFFFF, p12, o);
        p21 += __shfl_xor_sync(0xFFFFFFFF, p21, o);
        p22 += __shfl_xor_sync(0xFFFFFFFF, p22, o);
    }
    float l0 = p11 + b11[0], l1 = p12 + b12[0];
    float m = fmaxf(l0, l1);
    float q0 = expf(l0 - m), q1 = expf(l1 - m);
    float inv = 1.0f / (q0 + q1);
    float s0 = q0 * inv, s1 = q1 * inv;
    t_ex[(size_t)node * DD + lane]      = s0 * a0 + s1 * c0;
    t_ex[(size_t)node * DD + lane + 32] = s0 * a1 + s1 * c1;
    float u0 = p21 + b21[0], u1 = p22 + b22[0];
    float m2 = fmaxf(u0, u1);
    float r0 = expf(u0 - m2), r1 = expf(u1 - m2);
    float inv2 = 1.0f / (r0 + r1);
    float t0 = r0 * inv2, t1 = r1 * inv2;
    t_im[(size_t)node * DD + lane]      = t0 * a0 + t1 * c0;
    t_im[(size_t)node * DD + lane + 32] = t0 * a1 + t1 * c1;
}

// ---------------- fused layer-2 on tensor cores (3xTF32), coalesced gather ----------
#define AS_STR 68
#define BS_STR 72
__global__ __launch_bounds__(256)
void l2_fused_tc(const float* __restrict__ t, const int* __restrict__ ssrc,
                 const int* __restrict__ offs, const int* __restrict__ bs2,
                 const float* __restrict__ W2, const float* __restrict__ root2,
                 const float* __restrict__ b2, const float* __restrict__ x1,
                 float* __restrict__ out, int R, int E) {
    extern __shared__ float sm[];
    float* As  = sm;                        // 128*68
    float* Bhi = sm + 128 * AS_STR;         // 64*72
    float* Blo = Bhi + 64 * BS_STR;         // 64*72
    int tid  = threadIdx.x;
    int lane = tid & 31, warp = tid >> 5;
    int lr = lane >> 2;
    int lc = lane & 3;
    int row0 = blockIdx.x * 128;
    int rip = tid >> 4;
    int c4  = tid & 15;
    int nk  = NN * R;

    float acc[8][4];
    #pragma unroll
    for (int i = 0; i < 8; i++)
        #pragma unroll
        for (int j = 0; j < 4; j++) acc[i][j] = 0.0f;

    for (int r = 0; r <= R; r++) {
        const float* B = (r < R) ? (W2 + (size_t)r * 4096) : root2;
        #pragma unroll
        for (int i = 0; i < 4; i++) {
            int f = tid + i * 256;
            int k = f >> 4, n4 = (f & 15) * 4;
            float4 v = reinterpret_cast<const float4*>(B)[f];
            float h0 = __uint_as_float(f2tf(v.x));
            float h1 = __uint_as_float(f2tf(v.y));
            float h2 = __uint_as_float(f2tf(v.z));
            float h3 = __uint_as_float(f2tf(v.w));
            int o = k * BS_STR + n4;
            Bhi[o + 0] = h0; Bhi[o + 1] = h1; Bhi[o + 2] = h2; Bhi[o + 3] = h3;
            Blo[o + 0] = __uint_as_float(f2tf(v.x - h0));
            Blo[o + 1] = __uint_as_float(f2tf(v.y - h1));
            Blo[o + 2] = __uint_as_float(f2tf(v.z - h2));
            Blo[o + 3] = __uint_as_float(f2tf(v.w - h3));
        }
        #pragma unroll
        for (int p = 0; p < 8; p++) {
            int arow = p * 16 + rip;
            int d_g  = row0 + arow;
            float4 s = make_float4(0.f, 0.f, 0.f, 0.f);
            if (d_g < NN) {
                if (r < R) {
                    int key = d_g * R + r;
                    int beg = seg_off(offs, bs2, key, nk, E);
                    int end = seg_off(offs, bs2, key + 1, nk, E);
                    for (int e = beg; e < end; e++) {
                        float4 v = reinterpret_cast<const float4*>(t)[(size_t)ssrc[e] * 16 + c4];
                        s.x += v.x; s.y += v.y; s.z += v.z; s.w += v.w;
                    }
                    if (end > beg) {
                        float iv = 1.0f / (float)(end - beg);
                        s.x *= iv; s.y *= iv; s.z *= iv; s.w *= iv;
                    }
                } else {
                    s = reinterpret_cast<const float4*>(t)[(size_t)d_g * 16 + c4];
                }
            }
            *reinterpret_cast<float4*>(&As[arow * AS_STR + c4 * 4]) = s;
        }
        __syncthreads();
        #pragma unroll
        for (int k0 = 0; k0 < 8; k0++) {
            int ab = (warp * 16 + lr) * AS_STR + k0 * 8 + lc;
            float a0 = As[ab];
            float a1 = As[ab + 8 * AS_STR];
            float a2 = As[ab + 4];
            float a3 = As[ab + 8 * AS_STR + 4];
            unsigned ahi[4], alo[4];
            ahi[0] = f2tf(a0); alo[0] = f2tf(a0 - __uint_as_float(ahi[0]));
            ahi[1] = f2tf(a1); alo[1] = f2tf(a1 - __uint_as_float(ahi[1]));
            ahi[2] = f2tf(a2); alo[2] = f2tf(a2 - __uint_as_float(ahi[2]));
            ahi[3] = f2tf(a3); alo[3] = f2tf(a3 - __uint_as_float(ahi[3]));
            #pragma unroll
            for (int n0 = 0; n0 < 8; n0++) {
                int bb = (k0 * 8 + lc) * BS_STR + n0 * 8 + lr;
                unsigned bh0 = __float_as_uint(Bhi[bb]);
                unsigned bh1 = __float_as_uint(Bhi[bb + 4 * BS_STR]);
                unsigned bl0 = __float_as_uint(Blo[bb]);
                unsigned bl1 = __float_as_uint(Blo[bb + 4 * BS_STR]);
                mma8(acc[n0], ahi, bh0, bh1);
                mma8(acc[n0], ahi, bl0, bl1);
                mma8(acc[n0], alo, bh0, bh1);
            }
        }
        __syncthreads();
    }
    int gr0 = row0 + warp * 16 + lr;
    int gr1 = gr0 + 8;
    #pragma unroll
    for (int n0 = 0; n0 < 8; n0++) {
        int c = n0 * 8 + 2 * lc;
        if (gr0 < NN) {
            out[(size_t)gr0 * 64 + c]     = acc[n0][0] + b2[c]     + x1[(size_t)gr0 * 64 + c];
            out[(size_t)gr0 * 64 + c + 1] = acc[n0][1] + b2[c + 1] + x1[(size_t)gr0 * 64 + c + 1];
        }
        if (gr1 < NN) {
            out[(size_t)gr1 * 64 + c]     = acc[n0][2] + b2[c]     + x1[(size_t)gr1 * 64 + c];
            out[(size_t)gr1 * 64 + c + 1] = acc[n0][3] + b2[c + 1] + x1[(size_t)gr1 * 64 + c + 1];
        }
    }
}

// ---------------- fused MLP: out = (leaky([ex|im] @ W1 + b1)) @ W2 + b2 --------------
__global__ void mlp_fused(const float* __restrict__ ex, const float* __restrict__ im,
                          const float* __restrict__ W1, const float* __restrict__ b1,
                          const float* __restrict__ W2, const float* __restrict__ b2,
                          float* __restrict__ C, int nrows) {
    __shared__ float As[128][64];
    __shared__ float Bs[64][64];
    int row0 = blockIdx.x * 128;
    int tid  = threadIdx.x;
    int tx = tid & 15, ty = tid >> 4;
    float acc[8][4];
    #pragma unroll
    for (int i = 0; i < 8; i++)
        #pragma unroll
        for (int j = 0; j < 4; j++) acc[i][j] = 0.0f;

    for (int kb = 0; kb < 2; kb++) {
        const float* A = kb ? im : ex;
        const float* B = W1 + (size_t)kb * 4096;
        #pragma unroll
        for (int i = 0; i < 8; i++) {
            int f = tid + i * 256;
            int rr = f >> 4, c4 = f & 15;
            int gr = row0 + rr;
            float4 v = make_float4(0.f, 0.f, 0.f, 0.f);
            if (gr < nrows)
                v = *reinterpret_cast<const float4*>(A + (size_t)gr * 64 + c4 * 4);
            *reinterpret_cast<float4*>(&As[rr][c4 * 4]) = v;
        }
        #pragma unroll
        for (int i = 0; i < 4; i++) {
            int f = tid + i * 256;
            int rr = f >> 4, c4 = f & 15;
            float4 v = *reinterpret_cast<const float4*>(B + rr * 64 + c4 * 4);
            *reinterpret_cast<float4*>(&Bs[rr][c4 * 4]) = v;
        }
        __syncthreads();
        #pragma unroll 4
        for (int k = 0; k < 64; k++) {
            float b0v = Bs[k][tx * 4 + 0];
            float b1v = Bs[k][tx * 4 + 1];
            float b2v = Bs[k][tx * 4 + 2];
            float b3v = Bs[k][tx * 4 + 3];
            #pragma unroll
            for (int i = 0; i < 8; i++) {
                float a = As[ty * 8 + i][k];
                acc[i][0] += a * b0v;
                acc[i][1] += a * b1v;
                acc[i][2] += a * b2v;
                acc[i][3] += a * b3v;
            }
        }
        __syncthreads();
    }
    #pragma unroll
    for (int i = 0; i < 8; i++) {
        int rr = ty * 8 + i;
        #pragma unroll
        for (int j = 0; j < 4; j++) {
            int c = tx * 4 + j;
            float v = acc[i][j] + b1[c];
            v = (v > 0.0f) ? v : 0.01f * v;
            As[rr][c] = v;
            acc[i][j] = 0.0f;
        }
    }
    #pragma unroll
    for (int i = 0; i < 4; i++) {
        int f = tid + i * 256;
        int rr = f >> 4, c4 = f & 15;
        float4 v = *reinterpret_cast<const float4*>(W2 + rr * 64 + c4 * 4);
        *reinterpret_cast<float4*>(&Bs[rr][c4 * 4]) = v;
    }
    __syncthreads();
    #pragma unroll 4
    for (int k = 0; k < 64; k++) {
        float b0v = Bs[k][tx * 4 + 0];
        float b1v = Bs[k][tx * 4 + 1];
        float b2v = Bs[k][tx * 4 + 2];
        float b3v = Bs[k][tx * 4 + 3];
        #pragma unroll
        for (int i = 0; i < 8; i++) {
            float a = As[ty * 8 + i][k];
            acc[i][0] += a * b0v;
            acc[i][1] += a * b1v;
            acc[i][2] += a * b2v;
            acc[i][3] += a * b3v;
        }
    }
    #pragma unroll
    for (int i = 0; i < 8; i++) {
        int gr = row0 + ty * 8 + i;
        if (gr >= nrows) continue;
        #pragma unroll
        for (int j = 0; j < 4; j++) {
            int c = tx * 4 + j;
            C[(size_t)gr * 64 + c] = acc[i][j] + b2[c];
        }
    }
}

// ---------------- host ----------------
extern "C" void kernel_launch(void* const* d_in, const int* in_sizes, int n_in,
                              void* d_out, int out_size) {
    (void)in_sizes; (void)n_in; (void)out_size;
    const int*   ei_ex   = (const int*)d_in[0];
    const int*   et_ex   = (const int*)d_in[1];
    const int*   ei_im   = (const int*)d_in[2];
    const int*   et_im   = (const int*)d_in[3];
    const float* W1_ex   = (const float*)d_in[4];
    const float* root1_ex= (const float*)d_in[5];
    const float* b1_ex   = (const float*)d_in[6];
    const float* W1_im   = (const float*)d_in[7];
    const float* root1_im= (const float*)d_in[8];
    const float* b1_im   = (const float*)d_in[9];
    const float* W2_ex   = (const float*)d_in[10];
    const float* root2_ex= (const float*)d_in[11];
    const float* b2_ex   = (const float*)d_in[12];
    const float* W2_im   = (const float*)d_in[13];
    const float* root2_im= (const float*)d_in[14];
    const float* b2_im   = (const float*)d_in[15];
    const float* aw11 = (const float*)d_in[16]; const float* ab11 = (const float*)d_in[17];
    const float* aw12 = (const float*)d_in[18]; const float* ab12 = (const float*)d_in[19];
    const float* aw21 = (const float*)d_in[20]; const float* ab21 = (const float*)d_in[21];
    const float* aw22 = (const float*)d_in[22]; const float* ab22 = (const float*)d_in[23];
    const float* agg_W1 = (const float*)d_in[24]; const float* agg_b1 = (const float*)d_in[25];
    const float* agg_W2 = (const float*)d_in[26]; const float* agg_b2 = (const float*)d_in[27];
    float* out = (float*)d_out;

    const int* src_ex = ei_ex;
    const int* dst_ex = ei_ex + EEX;
    const int* src_im = ei_im;
    const int* dst_im = ei_im + EIM;

    void *p_cnt_ex, *p_cnt_im, *p_offs_ex, *p_offs_im, *p_cur_ex, *p_cur_im,
         *p_bs_ex, *p_bs_im, *p_bs2_ex, *p_bs2_im, *p_ticket, *p_ssrc_ex, *p_ssrc_im,
         *p_ex_x1, *p_im_x1, *p_t_ex, *p_t_im, *p_ex_sum, *p_im_sum;
    cudaGetSymbolAddress(&p_cnt_ex, g_cnt_ex);
    cudaGetSymbolAddress(&p_cnt_im, g_cnt_im);
    cudaGetSymbolAddress(&p_offs_ex, g_offs_ex);
    cudaGetSymbolAddress(&p_offs_im, g_offs_im);
    cudaGetSymbolAddress(&p_cur_ex, g_cur_ex);
    cudaGetSymbolAddress(&p_cur_im, g_cur_im);
    cudaGetSymbolAddress(&p_bs_ex, g_bs_ex);
    cudaGetSymbolAddress(&p_bs_im, g_bs_im);
    cudaGetSymbolAddress(&p_bs2_ex, g_bs2_ex);
    cudaGetSymbolAddress(&p_bs2_im, g_bs2_im);
    cudaGetSymbolAddress(&p_ticket, g_ticket);
    cudaGetSymbolAddress(&p_ssrc_ex, g_ssrc_ex);
    cudaGetSymbolAddress(&p_ssrc_im, g_ssrc_im);
    cudaGetSymbolAddress(&p_ex_x1, g_ex_x1);
    cudaGetSymbolAddress(&p_im_x1, g_im_x1);
    cudaGetSymbolAddress(&p_t_ex, g_t_ex);
    cudaGetSymbolAddress(&p_t_im, g_t_im);
    cudaGetSymbolAddress(&p_ex_sum, g_ex_sum);
    cudaGetSymbolAddress(&p_im_sum, g_im_sum);

    // zero counts + ticket (memsets don't count as kernel launches)
    cudaMemsetAsync(p_cnt_ex, 0, sizeof(int) * NRE);
    cudaMemsetAsync(p_cnt_im, 0, sizeof(int) * NRI);
    cudaMemsetAsync(p_ticket, 0, sizeof(int));

    // kernel 1: counts (both edge sets)
    count_both<<<(EEX + EIM + 255) / 256, 256>>>(dst_ex, et_ex, dst_im, et_im,
                                                 (int*)p_cnt_ex, (int*)p_cnt_im);

    // kernel 2: fused scan (intra offsets + last-block bs2 scan)
    scan_fused<<<NBE + NBI, 256>>>((const int*)p_cnt_ex, (int*)p_offs_ex, (int*)p_cur_ex,
                                   (int*)p_bs_ex, (int*)p_bs2_ex,
                                   (const int*)p_cnt_im, (int*)p_offs_im, (int*)p_cur_im,
                                   (int*)p_bs_im, (int*)p_bs2_im,
                                   (int*)p_ticket);

    // kernel 3: counting sort (two-level positions)
    sort_both<<<(EEX + EIM + 255) / 256, 256>>>(src_ex, dst_ex, et_ex, src_im, dst_im, et_im,
                                                (int*)p_cur_ex, (const int*)p_bs2_ex,
                                                (int*)p_ssrc_ex,
                                                (int*)p_cur_im, (const int*)p_bs2_im,
                                                (int*)p_ssrc_im);

    // kernel 4 (PROFILED): layer-1 aggregation ex
    agg_l1<<<(NN * 16 + 255) / 256, 256>>>(W1_ex, (const int*)p_ssrc_ex,
                                           (const int*)p_offs_ex, (const int*)p_bs2_ex,
                                           root1_ex, b1_ex, (float*)p_ex_x1, REX, EEX);
    // kernel 5: layer-1 aggregation im
    agg_l1<<<(NN * 16 + 255) / 256, 256>>>(W1_im, (const int*)p_ssrc_im,
                                           (const int*)p_offs_im, (const int*)p_bs2_im,
                                           root1_im, b1_im, (float*)p_im_x1, RIM, EIM);

    // kernel 6: ATTITU fusion
    attitu_kernel<<<(NN * 32 + 255) / 256, 256>>>((const float*)p_ex_x1, (const float*)p_im_x1,
                                                  aw11, ab11, aw12, ab12, aw21, ab21, aw22, ab22,
                                                  (float*)p_t_ex, (float*)p_t_im, NN);

    const int tiles128 = (NN + 127) / 128;    // 782
    const int smem_tc = (128 * AS_STR + 2 * 64 * BS_STR) * sizeof(float);  // 71680 B

    // kernels 7,8: fused layer-2 on tensor cores
    cudaFuncSetAttribute(l2_fused_tc, cudaFuncAttributeMaxDynamicSharedMemorySize, smem_tc);
    l2_fused_tc<<<tiles128, 256, smem_tc>>>((const float*)p_t_ex, (const int*)p_ssrc_ex,
                                            (const int*)p_offs_ex, (const int*)p_bs2_ex,
                                            W2_ex, root2_ex, b2_ex,
                                            (const float*)p_ex_x1, (float*)p_ex_sum, REX, EEX);
    l2_fused_tc<<<tiles128, 256, smem_tc>>>((const float*)p_t_im, (const int*)p_ssrc_im,
                                            (const int*)p_offs_im, (const int*)p_bs2_im,
                                            W2_im, root2_im, b2_im,
                                            (const float*)p_im_x1, (float*)p_im_sum, RIM, EIM);

    // kernel 9: fused MLP -> writes d_out directly
    mlp_fused<<<tiles128, 256>>>((const float*)p_ex_sum, (const float*)p_im_sum,
                                 agg_W1, agg_b1, agg_W2, agg_b2, out, NN);
}

// round 14
// speedup vs baseline: 1.2214x; 1.2214x over previous
#include <cuda_runtime.h>
#include <cuda_bf16.h>
#include <cstddef>
#include <cstdint>

#define NN  100000
#define DD  64
#define REX 8
#define RIM 4
#define EEX 2000000
#define EIM 1000000
#define NRE (NN * REX)               // 800000
#define NRI (NN * RIM)               // 400000
#define NBE ((NRE + 1023) / 1024)    // 782
#define NBI ((NRI + 1023) / 1024)    // 391

// ---------------- scratch (static device globals; no allocation) ----------------
__device__ int   g_cnt_ex[NRE];
__device__ int   g_cnt_im[NRI];
__device__ int   g_offs_ex[NRE];
__device__ int   g_offs_im[NRI];
__device__ int   g_cur_ex[NRE];
__device__ int   g_cur_im[NRI];
__device__ int   g_bs_ex[1024];
__device__ int   g_bs_im[1024];
__device__ int   g_ssrc_ex[EEX];
__device__ int   g_ssrc_im[EIM];
__device__ float g_ex_x1[NN * DD];
__device__ float g_im_x1[NN * DD];
__device__ float g_t_ex[NN * DD];
__device__ float g_t_im[NN * DD];
__device__ float g_ex_sum[NN * DD];
__device__ float g_im_sum[NN * DD];

// ---------------- bf16 helpers ----------------
// pack two floats as bf16x2: low half = lo, high half = hi
__device__ __forceinline__ unsigned pack_bf16(float lo, float hi) {
    unsigned r;
    asm("cvt.rn.bf16x2.f32 %0, %1, %2;" : "=r"(r) : "f"(hi), "f"(lo));
    return r;
}

// split (v0, v1) into bf16 hi-plane packed word and residual lo-plane packed word
__device__ __forceinline__ void splitpack(float v0, float v1, unsigned& ph, unsigned& pl) {
    float h0 = __bfloat162float(__float2bfloat16(v0));
    float h1 = __bfloat162float(__float2bfloat16(v1));
    ph = pack_bf16(h0, h1);
    pl = pack_bf16(v0 - h0, v1 - h1);
}

__device__ __forceinline__ void mma16(float* c, const unsigned* a, unsigned b0, unsigned b1) {
    asm volatile("mma.sync.aligned.m16n8k16.row.col.f32.bf16.bf16.f32 "
                 "{%0,%1,%2,%3}, {%4,%5,%6,%7}, {%8,%9}, {%0,%1,%2,%3};"
                 : "+f"(c[0]), "+f"(c[1]), "+f"(c[2]), "+f"(c[3])
                 : "r"(a[0]), "r"(a[1]), "r"(a[2]), "r"(a[3]), "r"(b0), "r"(b1));
}

// ---------------- kernel 1: count per (dst, relation), both edge sets ----------------
__global__ void count_both(const int* __restrict__ dst_ex, const int* __restrict__ et_ex,
                           const int* __restrict__ dst_im, const int* __restrict__ et_im,
                           int* __restrict__ ce, int* __restrict__ ci) {
    int i = blockIdx.x * blockDim.x + threadIdx.x;
    if (i < EEX) {
        atomicAdd(&ce[dst_ex[i] * REX + et_ex[i]], 1);
    } else if (i < EEX + EIM) {
        int e = i - EEX;
        atomicAdd(&ci[dst_im[e] * RIM + et_im[e]], 1);
    }
}

// ---------------- kernel 2: level-1 scan (intra-block excl), both arrays -------------
__global__ void scan1_both(const int* __restrict__ in_ex, int* __restrict__ out_ex,
                           int* __restrict__ bsum_ex,
                           const int* __restrict__ in_im, int* __restrict__ out_im,
                           int* __restrict__ bsum_im) {
    __shared__ int s[256];
    int b = blockIdx.x;
    const int* in; int* out; int* bsum; int idx; int n;
    if (b < NBE) { in = in_ex; out = out_ex; bsum = bsum_ex; idx = b;       n = NRE; }
    else         { in = in_im; out = out_im; bsum = bsum_im; idx = b - NBE; n = NRI; }
    int t = threadIdx.x;
    int base = idx * 1024 + t * 4;
    int v0 = (base     < n) ? in[base]     : 0;
    int v1 = (base + 1 < n) ? in[base + 1] : 0;
    int v2 = (base + 2 < n) ? in[base + 2] : 0;
    int v3 = (base + 3 < n) ? in[base + 3] : 0;
    int tot = v0 + v1 + v2 + v3;
    s[t] = tot;
    __syncthreads();
    #pragma unroll
    for (int o = 1; o < 256; o <<= 1) {
        int x = (t >= o) ? s[t - o] : 0;
        __syncthreads();
        s[t] += x;
        __syncthreads();
    }
    int excl = s[t] - tot;
    if (base     < n) out[base]     = excl;
    if (base + 1 < n) out[base + 1] = excl + v0;
    if (base + 2 < n) out[base + 2] = excl + v0 + v1;
    if (base + 3 < n) out[base + 3] = excl + v0 + v1 + v2;
    if (t == 255) bsum[idx] = s[255];
}

// ---------------- kernel 3: add global block base; write offs AND cur -----------------
__global__ void scan_add2_both(const int* __restrict__ bsum_ex, int* __restrict__ offs_ex,
                               int* __restrict__ cur_ex,
                               const int* __restrict__ bsum_im, int* __restrict__ offs_im,
                               int* __restrict__ cur_im) {
    __shared__ int sred[256];
    int b = blockIdx.x;
    const int* bsum; int* offs; int* cur; int idx; int n;
    if (b < NBE) { bsum = bsum_ex; offs = offs_ex; cur = cur_ex; idx = b;       n = NRE; }
    else         { bsum = bsum_im; offs = offs_im; cur = cur_im; idx = b - NBE; n = NRI; }
    int t = threadIdx.x;
    int partial = 0;
    for (int j = t; j < idx; j += 256) partial += bsum[j];
    sred[t] = partial;
    __syncthreads();
    #pragma unroll
    for (int o = 128; o > 0; o >>= 1) {
        if (t < o) sred[t] += sred[t + o];
        __syncthreads();
    }
    int base = sred[0];
    int g = idx * 1024 + t * 4;
    #pragma unroll
    for (int k = 0; k < 4; k++) {
        if (g + k < n) {
            int v = offs[g + k] + base;
            offs[g + k] = v;
            cur[g + k]  = v;
        }
    }
}

// ---------------- kernel 4: counting sort, both edge sets ----------------
__global__ void sort_both(const int* __restrict__ src_ex, const int* __restrict__ dst_ex,
                          const int* __restrict__ et_ex,
                          const int* __restrict__ src_im, const int* __restrict__ dst_im,
                          const int* __restrict__ et_im,
                          int* __restrict__ cur_ex, int* __restrict__ ssrc_ex,
                          int* __restrict__ cur_im, int* __restrict__ ssrc_im) {
    int i = blockIdx.x * blockDim.x + threadIdx.x;
    if (i < EEX) {
        int key = dst_ex[i] * REX + et_ex[i];
        int pos = atomicAdd(&cur_ex[key], 1);
        ssrc_ex[pos] = src_ex[i];
    } else if (i < EEX + EIM) {
        int e = i - EEX;
        int key = dst_im[e] * RIM + et_im[e];
        int pos = atomicAdd(&cur_im[key], 1);
        ssrc_im[pos] = src_im[e];
    }
}

// ---------------- kernels 5,6: layer-1 aggregate (owner-write, no atomics) -----------
__global__ void agg_l1(const float* __restrict__ W, const int* __restrict__ ssrc,
                       const int* __restrict__ offs, const float* __restrict__ root,
                       const float* __restrict__ bias, float* __restrict__ out,
                       int R, int E) {
    int idx  = blockIdx.x * blockDim.x + threadIdx.x;
    int d    = idx >> 4;
    int lane = idx & 15;
    if (d >= NN) return;
    float4 b = reinterpret_cast<const float4*>(bias)[lane];
    float4 acc = reinterpret_cast<const float4*>(root)[(size_t)d * 16 + lane];
    acc.x += b.x; acc.y += b.y; acc.z += b.z; acc.w += b.w;
    int beg = offs[d * R];
    for (int r = 0; r < R; r++) {
        int key = d * R + r;
        int end = (key + 1 < NN * R) ? offs[key + 1] : E;
        if (end > beg) {
            float4 s = make_float4(0.f, 0.f, 0.f, 0.f);
            for (int e = beg; e < end; e++) {
                int sv = ssrc[e];
                float4 v = reinterpret_cast<const float4*>(W)[((size_t)r * NN + sv) * 16 + lane];
                s.x += v.x; s.y += v.y; s.z += v.z; s.w += v.w;
            }
            float inv = 1.0f / (float)(end - beg);
            acc.x += s.x * inv; acc.y += s.y * inv; acc.z += s.z * inv; acc.w += s.w * inv;
        }
        beg = end;
    }
    reinterpret_cast<float4*>(out)[(size_t)d * 16 + lane] = acc;
}

// ---------------- ATTITU fusion (warp per node) ----------------
__global__ void attitu_kernel(const float* __restrict__ ex1, const float* __restrict__ im1,
                              const float* __restrict__ w11, const float* __restrict__ b11,
                              const float* __restrict__ w12, const float* __restrict__ b12,
                              const float* __restrict__ w21, const float* __restrict__ b21,
                              const float* __restrict__ w22, const float* __restrict__ b22,
                              float* __restrict__ t_ex, float* __restrict__ t_im, int nnodes) {
    int g    = blockIdx.x * blockDim.x + threadIdx.x;
    int node = g >> 5;
    int lane = g & 31;
    if (node >= nnodes) return;
    const float* e1 = ex1 + (size_t)node * DD;
    const float* e2 = im1 + (size_t)node * DD;
    float a0 = e1[lane], a1 = e1[lane + 32];
    float c0 = e2[lane], c1 = e2[lane + 32];
    float p11 = a0 * w11[lane] + a1 * w11[lane + 32];
    float p12 = c0 * w12[lane] + c1 * w12[lane + 32];
    float p21 = a0 * w21[lane] + a1 * w21[lane + 32];
    float p22 = c0 * w22[lane] + c1 * w22[lane + 32];
    #pragma unroll
    for (int o = 16; o > 0; o >>= 1) {
        p11 += __shfl_xor_sync(0xFFFFFFFF, p11, o);
        p12 += __shfl_xor_sync(0xFFFFFFFF, p12, o);
        p21 += __shfl_xor_sync(0xFFFFFFFF, p21, o);
        p22 += __shfl_xor_sync(0xFFFFFFFF, p22, o);
    }
    float l0 = p11 + b11[0], l1 = p12 + b12[0];
    float m = fmaxf(l0, l1);
    float q0 = expf(l0 - m), q1 = expf(l1 - m);
    float inv = 1.0f / (q0 + q1);
    float s0 = q0 * inv, s1 = q1 * inv;
    t_ex[(size_t)node * DD + lane]      = s0 * a0 + s1 * c0;
    t_ex[(size_t)node * DD + lane + 32] = s0 * a1 + s1 * c1;
    float u0 = p21 + b21[0], u1 = p22 + b22[0];
    float m2 = fmaxf(u0, u1);
    float r0 = expf(u0 - m2), r1 = expf(u1 - m2);
    float inv2 = 1.0f / (r0 + r1);
    float t0 = r0 * inv2, t1 = r1 * inv2;
    t_im[(size_t)node * DD + lane]      = t0 * a0 + t1 * c0;
    t_im[(size_t)node * DD + lane + 32] = t0 * a1 + t1 * c1;
}

// ---------------- fused layer-2, bf16x3 m16n8k16 tensor cores ----------
// out = x1 + b2 + t@root2 + sum_r mean_r(t) @ W2[r]
#define AS_STR 68
#define BP_STR 72
// smem: As fp32[128*68] + Bph u32[32*72] + Bpl u32[32*72] = 53248 B
__global__ __launch_bounds__(256)
void l2_fused_tc(const float* __restrict__ t, const int* __restrict__ ssrc,
                 const int* __restrict__ offs,
                 const float* __restrict__ W2, const float* __restrict__ root2,
                 const float* __restrict__ b2, const float* __restrict__ x1,
                 float* __restrict__ out, int R, int E) {
    extern __shared__ float sm[];
    float*    As  = sm;                                   // 128*68 fp32
    unsigned* Bph = reinterpret_cast<unsigned*>(sm + 128 * AS_STR);   // 32*72
    unsigned* Bpl = Bph + 32 * BP_STR;                    // 32*72
    int tid  = threadIdx.x;
    int lane = tid & 31, warp = tid >> 5;
    int lr = lane >> 2;                     // 0..7 (group id)
    int lc = lane & 3;                      // 0..3 (thread in group)
    int row0 = blockIdx.x * 128;
    int rip = tid >> 4;                     // gather: row-in-pass 0..15
    int c4  = tid & 15;                     // gather: float4 chunk 0..15

    float acc[8][4];
    #pragma unroll
    for (int i = 0; i < 8; i++)
        #pragma unroll
        for (int j = 0; j < 4; j++) acc[i][j] = 0.0f;

    for (int r = 0; r <= R; r++) {
        // ---- B tile: read 64x64 fp32, pack k-pairs as bf16x2 hi/lo planes ----
        const float* B = (r < R) ? (W2 + (size_t)r * 4096) : root2;
        #pragma unroll
        for (int i = 0; i < 2; i++) {
            int idx = tid + i * 256;        // 0..511
            int kk = idx >> 4;              // 0..31 (k-pair index)
            int n4 = (idx & 15) * 4;
            float4 r0 = *reinterpret_cast<const float4*>(B + (size_t)(2 * kk) * 64 + n4);
            float4 r1 = *reinterpret_cast<const float4*>(B + (size_t)(2 * kk + 1) * 64 + n4);
            int o = kk * BP_STR + n4;
            splitpack(r0.x, r1.x, Bph[o + 0], Bpl[o + 0]);
            splitpack(r0.y, r1.y, Bph[o + 1], Bpl[o + 1]);
            splitpack(r0.z, r1.z, Bph[o + 2], Bpl[o + 2]);
            splitpack(r0.w, r1.w, Bph[o + 3], Bpl[o + 3]);
        }
        // ---- A tile: gather-mean, 16 threads per row (coalesced 256B rows) ----
        #pragma unroll
        for (int p = 0; p < 8; p++) {
            int arow = p * 16 + rip;
            int d_g  = row0 + arow;
            float4 s = make_float4(0.f, 0.f, 0.f, 0.f);
            if (d_g < NN) {
                if (r < R) {
                    int key = d_g * R + r;
                    int beg = offs[key];
                    int end = (key + 1 < NN * R) ? offs[key + 1] : E;
                    for (int e = beg; e < end; e++) {
                        float4 v = reinterpret_cast<const float4*>(t)[(size_t)ssrc[e] * 16 + c4];
                        s.x += v.x; s.y += v.y; s.z += v.z; s.w += v.w;
                    }
                    if (end > beg) {
                        float iv = 1.0f / (float)(end - beg);
                        s.x *= iv; s.y *= iv; s.z *= iv; s.w *= iv;
                    }
                } else {
                    s = reinterpret_cast<const float4*>(t)[(size_t)d_g * 16 + c4];
                }
            }
            *reinterpret_cast<float4*>(&As[arow * AS_STR + c4 * 4]) = s;
        }
        __syncthreads();
        // ---- mma: 4 k16-steps x 8 n-tiles, bf16x3 ----
        #pragma unroll
        for (int k0 = 0; k0 < 4; k0++) {
            int ab = (warp * 16 + lr) * AS_STR + k0 * 16 + 2 * lc;
            float2 p0 = *reinterpret_cast<const float2*>(&As[ab]);                   // a0
            float2 p1 = *reinterpret_cast<const float2*>(&As[ab + 8 * AS_STR]);      // a1
            float2 p2 = *reinterpret_cast<const float2*>(&As[ab + 8]);               // a2
            float2 p3 = *reinterpret_cast<const float2*>(&As[ab + 8 * AS_STR + 8]);  // a3
            unsigned ahi[4], alo[4];
            splitpack(p0.x, p0.y, ahi[0], alo[0]);
            splitpack(p1.x, p1.y, ahi[1], alo[1]);
            splitpack(p2.x, p2.y, ahi[2], alo[2]);
            splitpack(p3.x, p3.y, ahi[3], alo[3]);
            #pragma unroll
            for (int n0 = 0; n0 < 8; n0++) {
                int bb = (k0 * 8 + lc) * BP_STR + n0 * 8 + lr;
                unsigned bh0 = Bph[bb];
                unsigned bh1 = Bph[bb + 4 * BP_STR];
                unsigned bl0 = Bpl[bb];
                unsigned bl1 = Bpl[bb + 4 * BP_STR];
                mma16(acc[n0], ahi, bh0, bh1);
                mma16(acc[n0], ahi, bl0, bl1);
                mma16(acc[n0], alo, bh0, bh1);
            }
        }
        __syncthreads();
    }
    // ---- epilogue: + b2 + x1 (C-frag layout identical to tf32 path) ----
    int gr0 = row0 + warp * 16 + lr;
    int gr1 = gr0 + 8;
    #pragma unroll
    for (int n0 = 0; n0 < 8; n0++) {
        int c = n0 * 8 + 2 * lc;
        if (gr0 < NN) {
            out[(size_t)gr0 * 64 + c]     = acc[n0][0] + b2[c]     + x1[(size_t)gr0 * 64 + c];
            out[(size_t)gr0 * 64 + c + 1] = acc[n0][1] + b2[c + 1] + x1[(size_t)gr0 * 64 + c + 1];
        }
        if (gr1 < NN) {
            out[(size_t)gr1 * 64 + c]     = acc[n0][2] + b2[c]     + x1[(size_t)gr1 * 64 + c];
            out[(size_t)gr1 * 64 + c + 1] = acc[n0][3] + b2[c + 1] + x1[(size_t)gr1 * 64 + c + 1];
        }
    }
}

// ---------------- fused MLP: out = (leaky([ex|im] @ W1 + b1)) @ W2 + b2 --------------
__global__ void mlp_fused(const float* __restrict__ ex, const float* __restrict__ im,
                          const float* __restrict__ W1, const float* __restrict__ b1,
                          const float* __restrict__ W2, const float* __restrict__ b2,
                          float* __restrict__ C, int nrows) {
    __shared__ float As[128][64];
    __shared__ float Bs[64][64];
    int row0 = blockIdx.x * 128;
    int tid  = threadIdx.x;
    int tx = tid & 15, ty = tid >> 4;
    float acc[8][4];
    #pragma unroll
    for (int i = 0; i < 8; i++)
        #pragma unroll
        for (int j = 0; j < 4; j++) acc[i][j] = 0.0f;

    for (int kb = 0; kb < 2; kb++) {
        const float* A = kb ? im : ex;
        const float* B = W1 + (size_t)kb * 4096;
        #pragma unroll
        for (int i = 0; i < 8; i++) {
            int f = tid + i * 256;
            int rr = f >> 4, c4 = f & 15;
            int gr = row0 + rr;
            float4 v = make_float4(0.f, 0.f, 0.f, 0.f);
            if (gr < nrows)
                v = *reinterpret_cast<const float4*>(A + (size_t)gr * 64 + c4 * 4);
            *reinterpret_cast<float4*>(&As[rr][c4 * 4]) = v;
        }
        #pragma unroll
        for (int i = 0; i < 4; i++) {
            int f = tid + i * 256;
            int rr = f >> 4, c4 = f & 15;
            float4 v = *reinterpret_cast<const float4*>(B + rr * 64 + c4 * 4);
            *reinterpret_cast<float4*>(&Bs[rr][c4 * 4]) = v;
        }
        __syncthreads();
        #pragma unroll 4
        for (int k = 0; k < 64; k++) {
            float b0v = Bs[k][tx * 4 + 0];
            float b1v = Bs[k][tx * 4 + 1];
            float b2v = Bs[k][tx * 4 + 2];
            float b3v = Bs[k][tx * 4 + 3];
            #pragma unroll
            for (int i = 0; i < 8; i++) {
                float a = As[ty * 8 + i][k];
                acc[i][0] += a * b0v;
                acc[i][1] += a * b1v;
                acc[i][2] += a * b2v;
                acc[i][3] += a * b3v;
            }
        }
        __syncthreads();
    }
    #pragma unroll
    for (int i = 0; i < 8; i++) {
        int rr = ty * 8 + i;
        #pragma unroll
        for (int j = 0; j < 4; j++) {
            int c = tx * 4 + j;
            float v = acc[i][j] + b1[c];
            v = (v > 0.0f) ? v : 0.01f * v;
            As[rr][c] = v;
            acc[i][j] = 0.0f;
        }
    }
    #pragma unroll
    for (int i = 0; i < 4; i++) {
        int f = tid + i * 256;
        int rr = f >> 4, c4 = f & 15;
        float4 v = *reinterpret_cast<const float4*>(W2 + rr * 64 + c4 * 4);
        *reinterpret_cast<float4*>(&Bs[rr][c4 * 4]) = v;
    }
    __syncthreads();
    #pragma unroll 4
    for (int k = 0; k < 64; k++) {
        float b0v = Bs[k][tx * 4 + 0];
        float b1v = Bs[k][tx * 4 + 1];
        float b2v = Bs[k][tx * 4 + 2];
        float b3v = Bs[k][tx * 4 + 3];
        #pragma unroll
        for (int i = 0; i < 8; i++) {
            float a = As[ty * 8 + i][k];
            acc[i][0] += a * b0v;
            acc[i][1] += a * b1v;
            acc[i][2] += a * b2v;
            acc[i][3] += a * b3v;
        }
    }
    #pragma unroll
    for (int i = 0; i < 8; i++) {
        int gr = row0 + ty * 8 + i;
        if (gr >= nrows) continue;
        #pragma unroll
        for (int j = 0; j < 4; j++) {
            int c = tx * 4 + j;
            C[(size_t)gr * 64 + c] = acc[i][j] + b2[c];
        }
    }
}

// ---------------- host ----------------
extern "C" void kernel_launch(void* const* d_in, const int* in_sizes, int n_in,
                              void* d_out, int out_size) {
    (void)in_sizes; (void)n_in; (void)out_size;
    const int*   ei_ex   = (const int*)d_in[0];
    const int*   et_ex   = (const int*)d_in[1];
    const int*   ei_im   = (const int*)d_in[2];
    const int*   et_im   = (const int*)d_in[3];
    const float* W1_ex   = (const float*)d_in[4];
    const float* root1_ex= (const float*)d_in[5];
    const float* b1_ex   = (const float*)d_in[6];
    const float* W1_im   = (const float*)d_in[7];
    const float* root1_im= (const float*)d_in[8];
    const float* b1_im   = (const float*)d_in[9];
    const float* W2_ex   = (const float*)d_in[10];
    const float* root2_ex= (const float*)d_in[11];
    const float* b2_ex   = (const float*)d_in[12];
    const float* W2_im   = (const float*)d_in[13];
    const float* root2_im= (const float*)d_in[14];
    const float* b2_im   = (const float*)d_in[15];
    const float* aw11 = (const float*)d_in[16]; const float* ab11 = (const float*)d_in[17];
    const float* aw12 = (const float*)d_in[18]; const float* ab12 = (const float*)d_in[19];
    const float* aw21 = (const float*)d_in[20]; const float* ab21 = (const float*)d_in[21];
    const float* aw22 = (const float*)d_in[22]; const float* ab22 = (const float*)d_in[23];
    const float* agg_W1 = (const float*)d_in[24]; const float* agg_b1 = (const float*)d_in[25];
    const float* agg_W2 = (const float*)d_in[26]; const float* agg_b2 = (const float*)d_in[27];
    float* out = (float*)d_out;

    const int* src_ex = ei_ex;
    const int* dst_ex = ei_ex + EEX;
    const int* src_im = ei_im;
    const int* dst_im = ei_im + EIM;

    void *p_cnt_ex, *p_cnt_im, *p_offs_ex, *p_offs_im, *p_cur_ex, *p_cur_im,
         *p_bs_ex, *p_bs_im, *p_ssrc_ex, *p_ssrc_im,
         *p_ex_x1, *p_im_x1, *p_t_ex, *p_t_im, *p_ex_sum, *p_im_sum;
    cudaGetSymbolAddress(&p_cnt_ex, g_cnt_ex);
    cudaGetSymbolAddress(&p_cnt_im, g_cnt_im);
    cudaGetSymbolAddress(&p_offs_ex, g_offs_ex);
    cudaGetSymbolAddress(&p_offs_im, g_offs_im);
    cudaGetSymbolAddress(&p_cur_ex, g_cur_ex);
    cudaGetSymbolAddress(&p_cur_im, g_cur_im);
    cudaGetSymbolAddress(&p_bs_ex, g_bs_ex);
    cudaGetSymbolAddress(&p_bs_im, g_bs_im);
    cudaGetSymbolAddress(&p_ssrc_ex, g_ssrc_ex);
    cudaGetSymbolAddress(&p_ssrc_im, g_ssrc_im);
    cudaGetSymbolAddress(&p_ex_x1, g_ex_x1);
    cudaGetSymbolAddress(&p_im_x1, g_im_x1);
    cudaGetSymbolAddress(&p_t_ex, g_t_ex);
    cudaGetSymbolAddress(&p_t_im, g_t_im);
    cudaGetSymbolAddress(&p_ex_sum, g_ex_sum);
    cudaGetSymbolAddress(&p_im_sum, g_im_sum);

    // zero counts (memsets don't count as kernel launches)
    cudaMemsetAsync(p_cnt_ex, 0, sizeof(int) * NRE);
    cudaMemsetAsync(p_cnt_im, 0, sizeof(int) * NRI);

    // kernel 1: counts (both edge sets)
    count_both<<<(EEX + EIM + 255) / 256, 256>>>(dst_ex, et_ex, dst_im, et_im,
                                                 (int*)p_cnt_ex, (int*)p_cnt_im);

    // kernel 2: level-1 scan (both arrays)
    scan1_both<<<NBE + NBI, 256>>>((const int*)p_cnt_ex, (int*)p_offs_ex, (int*)p_bs_ex,
                                   (const int*)p_cnt_im, (int*)p_offs_im, (int*)p_bs_im);

    // kernel 3: globalize offsets; writes offs AND cur
    scan_add2_both<<<NBE + NBI, 256>>>((const int*)p_bs_ex, (int*)p_offs_ex, (int*)p_cur_ex,
                                       (const int*)p_bs_im, (int*)p_offs_im, (int*)p_cur_im);

    // kernel 4 (profiled): counting sort (both edge sets)
    sort_both<<<(EEX + EIM + 255) / 256, 256>>>(src_ex, dst_ex, et_ex, src_im, dst_im, et_im,
                                                (int*)p_cur_ex, (int*)p_ssrc_ex,
                                                (int*)p_cur_im, (int*)p_ssrc_im);

    // kernels 5,6: layer-1 aggregation
    agg_l1<<<(NN * 16 + 255) / 256, 256>>>(W1_ex, (const int*)p_ssrc_ex, (const int*)p_offs_ex,
                                           root1_ex, b1_ex, (float*)p_ex_x1, REX, EEX);
    agg_l1<<<(NN * 16 + 255) / 256, 256>>>(W1_im, (const int*)p_ssrc_im, (const int*)p_offs_im,
                                           root1_im, b1_im, (float*)p_im_x1, RIM, EIM);

    // kernel 7: ATTITU fusion
    attitu_kernel<<<(NN * 32 + 255) / 256, 256>>>((const float*)p_ex_x1, (const float*)p_im_x1,
                                                  aw11, ab11, aw12, ab12, aw21, ab21, aw22, ab22,
                                                  (float*)p_t_ex, (float*)p_t_im, NN);

    const int tiles128 = (NN + 127) / 128;    // 782
    const int smem_tc = 128 * AS_STR * (int)sizeof(float) + 2 * 32 * BP_STR * (int)sizeof(unsigned);  // 53248 B

    // kernels 8,9: fused layer-2, bf16x3 tensor cores
    cudaFuncSetAttribute(l2_fused_tc, cudaFuncAttributeMaxDynamicSharedMemorySize, smem_tc);
    l2_fused_tc<<<tiles128, 256, smem_tc>>>((const float*)p_t_ex, (const int*)p_ssrc_ex,
                                            (const int*)p_offs_ex, W2_ex, root2_ex, b2_ex,
                                            (const float*)p_ex_x1, (float*)p_ex_sum, REX, EEX);
    l2_fused_tc<<<tiles128, 256, smem_tc>>>((const float*)p_t_im, (const int*)p_ssrc_im,
                                            (const int*)p_offs_im, W2_im, root2_im, b2_im,
                                            (const float*)p_im_x1, (float*)p_im_sum, RIM, EIM);

    // kernel 10: fused MLP -> writes d_out directly
    mlp_fused<<<tiles128, 256>>>((const float*)p_ex_sum, (const float*)p_im_sum,
                                 agg_W1, agg_b1, agg_W2, agg_b2, out, NN);
}

// round 16
// speedup vs baseline: 1.2750x; 1.0439x over previous
#include <cuda_runtime.h>
#include <cuda_bf16.h>
#include <cstddef>
#include <cstdint>

#define NN  100000
#define DD  64
#define REX 8
#define RIM 4
#define EEX 2000000
#define EIM 1000000
#define NRE (NN * REX)               // 800000
#define NRI (NN * RIM)               // 400000
#define NBE ((NRE + 1023) / 1024)    // 782
#define NBI ((NRI + 1023) / 1024)    // 391

// ---------------- scratch (static device globals; no allocation) ----------------
__device__ int   g_cnt_ex[NRE];
__device__ int   g_cnt_im[NRI];
__device__ int   g_offs_ex[NRE];
__device__ int   g_offs_im[NRI];
__device__ int   g_cur_ex[NRE];
__device__ int   g_cur_im[NRI];
__device__ int   g_bs_ex[1024];
__device__ int   g_bs_im[1024];
__device__ int   g_ssrc_ex[EEX];
__device__ int   g_ssrc_im[EIM];
__device__ float g_ex_x1[NN * DD];
__device__ float g_im_x1[NN * DD];
__device__ float g_t_ex[NN * DD];
__device__ float g_t_im[NN * DD];
__device__ float g_ex_sum[NN * DD];
__device__ float g_im_sum[NN * DD];

// ---------------- bf16 helpers ----------------
__device__ __forceinline__ unsigned pack_bf16(float lo, float hi) {
    unsigned r;
    asm("cvt.rn.bf16x2.f32 %0, %1, %2;" : "=r"(r) : "f"(hi), "f"(lo));
    return r;
}

__device__ __forceinline__ void splitpack(float v0, float v1, unsigned& ph, unsigned& pl) {
    float h0 = __bfloat162float(__float2bfloat16(v0));
    float h1 = __bfloat162float(__float2bfloat16(v1));
    ph = pack_bf16(h0, h1);
    pl = pack_bf16(v0 - h0, v1 - h1);
}

__device__ __forceinline__ void mma16(float* c, const unsigned* a, unsigned b0, unsigned b1) {
    asm volatile("mma.sync.aligned.m16n8k16.row.col.f32.bf16.bf16.f32 "
                 "{%0,%1,%2,%3}, {%4,%5,%6,%7}, {%8,%9}, {%0,%1,%2,%3};"
                 : "+f"(c[0]), "+f"(c[1]), "+f"(c[2]), "+f"(c[3])
                 : "r"(a[0]), "r"(a[1]), "r"(a[2]), "r"(a[3]), "r"(b0), "r"(b1));
}

#define AS_STR 68
#define BP_STR 72

// load 64x64 fp32 B, pack k-pairs as bf16x2 hi/lo planes into smem
__device__ __forceinline__ void load_B_pack(const float* __restrict__ B,
                                            unsigned* Bph, unsigned* Bpl, int tid) {
    #pragma unroll
    for (int i = 0; i < 2; i++) {
        int idx = tid + i * 256;        // 0..511
        int kk = idx >> 4;              // 0..31 (k-pair index)
        int n4 = (idx & 15) * 4;
        float4 r0 = *reinterpret_cast<const float4*>(B + (size_t)(2 * kk) * 64 + n4);
        float4 r1 = *reinterpret_cast<const float4*>(B + (size_t)(2 * kk + 1) * 64 + n4);
        int o = kk * BP_STR + n4;
        splitpack(r0.x, r1.x, Bph[o + 0], Bpl[o + 0]);
        splitpack(r0.y, r1.y, Bph[o + 1], Bpl[o + 1]);
        splitpack(r0.z, r1.z, Bph[o + 2], Bpl[o + 2]);
        splitpack(r0.w, r1.w, Bph[o + 3], Bpl[o + 3]);
    }
}

// mma over the 128x64 fp32 As tile (bf16x3) into acc
__device__ __forceinline__ void mma_stage_bf16(const float* As, const unsigned* Bph,
                                               const unsigned* Bpl, float acc[8][4],
                                               int warp, int lr, int lc) {
    #pragma unroll
    for (int k0 = 0; k0 < 4; k0++) {
        int ab = (warp * 16 + lr) * AS_STR + k0 * 16 + 2 * lc;
        float2 p0 = *reinterpret_cast<const float2*>(&As[ab]);
        float2 p1 = *reinterpret_cast<const float2*>(&As[ab + 8 * AS_STR]);
        float2 p2 = *reinterpret_cast<const float2*>(&As[ab + 8]);
        float2 p3 = *reinterpret_cast<const float2*>(&As[ab + 8 * AS_STR + 8]);
        unsigned ahi[4], alo[4];
        splitpack(p0.x, p0.y, ahi[0], alo[0]);
        splitpack(p1.x, p1.y, ahi[1], alo[1]);
        splitpack(p2.x, p2.y, ahi[2], alo[2]);
        splitpack(p3.x, p3.y, ahi[3], alo[3]);
        #pragma unroll
        for (int n0 = 0; n0 < 8; n0++) {
            int bb = (k0 * 8 + lc) * BP_STR + n0 * 8 + lr;
            unsigned bh0 = Bph[bb];
            unsigned bh1 = Bph[bb + 4 * BP_STR];
            unsigned bl0 = Bpl[bb];
            unsigned bl1 = Bpl[bb + 4 * BP_STR];
            mma16(acc[n0], ahi, bh0, bh1);
            mma16(acc[n0], ahi, bl0, bl1);
            mma16(acc[n0], alo, bh0, bh1);
        }
    }
}

// ---------------- kernel 1: count per (dst, relation), both edge sets ----------------
__global__ void count_both(const int* __restrict__ dst_ex, const int* __restrict__ et_ex,
                           const int* __restrict__ dst_im, const int* __restrict__ et_im,
                           int* __restrict__ ce, int* __restrict__ ci) {
    int i = blockIdx.x * blockDim.x + threadIdx.x;
    if (i < EEX) {
        atomicAdd(&ce[dst_ex[i] * REX + et_ex[i]], 1);
    } else if (i < EEX + EIM) {
        int e = i - EEX;
        atomicAdd(&ci[dst_im[e] * RIM + et_im[e]], 1);
    }
}

// ---------------- kernel 2: level-1 scan (intra-block excl), both arrays -------------
__global__ void scan1_both(const int* __restrict__ in_ex, int* __restrict__ out_ex,
                           int* __restrict__ bsum_ex,
                           const int* __restrict__ in_im, int* __restrict__ out_im,
                           int* __restrict__ bsum_im) {
    __shared__ int s[256];
    int b = blockIdx.x;
    const int* in; int* out; int* bsum; int idx; int n;
    if (b < NBE) { in = in_ex; out = out_ex; bsum = bsum_ex; idx = b;       n = NRE; }
    else         { in = in_im; out = out_im; bsum = bsum_im; idx = b - NBE; n = NRI; }
    int t = threadIdx.x;
    int base = idx * 1024 + t * 4;
    int v0 = (base     < n) ? in[base]     : 0;
    int v1 = (base + 1 < n) ? in[base + 1] : 0;
    int v2 = (base + 2 < n) ? in[base + 2] : 0;
    int v3 = (base + 3 < n) ? in[base + 3] : 0;
    int tot = v0 + v1 + v2 + v3;
    s[t] = tot;
    __syncthreads();
    #pragma unroll
    for (int o = 1; o < 256; o <<= 1) {
        int x = (t >= o) ? s[t - o] : 0;
        __syncthreads();
        s[t] += x;
        __syncthreads();
    }
    int excl = s[t] - tot;
    if (base     < n) out[base]     = excl;
    if (base + 1 < n) out[base + 1] = excl + v0;
    if (base + 2 < n) out[base + 2] = excl + v0 + v1;
    if (base + 3 < n) out[base + 3] = excl + v0 + v1 + v2;
    if (t == 255) bsum[idx] = s[255];
}

// ---------------- kernel 3: add global block base; write offs AND cur -----------------
__global__ void scan_add2_both(const int* __restrict__ bsum_ex, int* __restrict__ offs_ex,
                               int* __restrict__ cur_ex,
                               const int* __restrict__ bsum_im, int* __restrict__ offs_im,
                               int* __restrict__ cur_im) {
    __shared__ int sred[256];
    int b = blockIdx.x;
    const int* bsum; int* offs; int* cur; int idx; int n;
    if (b < NBE) { bsum = bsum_ex; offs = offs_ex; cur = cur_ex; idx = b;       n = NRE; }
    else         { bsum = bsum_im; offs = offs_im; cur = cur_im; idx = b - NBE; n = NRI; }
    int t = threadIdx.x;
    int partial = 0;
    for (int j = t; j < idx; j += 256) partial += bsum[j];
    sred[t] = partial;
    __syncthreads();
    #pragma unroll
    for (int o = 128; o > 0; o >>= 1) {
        if (t < o) sred[t] += sred[t + o];
        __syncthreads();
    }
    int base = sred[0];
    int g = idx * 1024 + t * 4;
    #pragma unroll
    for (int k = 0; k < 4; k++) {
        if (g + k < n) {
            int v = offs[g + k] + base;
            offs[g + k] = v;
            cur[g + k]  = v;
        }
    }
}

// ---------------- kernel 4: counting sort, both edge sets ----------------
__global__ void sort_both(const int* __restrict__ src_ex, const int* __restrict__ dst_ex,
                          const int* __restrict__ et_ex,
                          const int* __restrict__ src_im, const int* __restrict__ dst_im,
                          const int* __restrict__ et_im,
                          int* __restrict__ cur_ex, int* __restrict__ ssrc_ex,
                          int* __restrict__ cur_im, int* __restrict__ ssrc_im) {
    int i = blockIdx.x * blockDim.x + threadIdx.x;
    if (i < EEX) {
        int key = dst_ex[i] * REX + et_ex[i];
        int pos = atomicAdd(&cur_ex[key], 1);
        ssrc_ex[pos] = src_ex[i];
    } else if (i < EEX + EIM) {
        int e = i - EEX;
        int key = dst_im[e] * RIM + et_im[e];
        int pos = atomicAdd(&cur_im[key], 1);
        ssrc_im[pos] = src_im[e];
    }
}

// ---------------- kernels 5,6: layer-1 aggregate (owner-write, no atomics) -----------
__global__ void agg_l1(const float* __restrict__ W, const int* __restrict__ ssrc,
                       const int* __restrict__ offs, const float* __restrict__ root,
                       const float* __restrict__ bias, float* __restrict__ out,
                       int R, int E) {
    int idx  = blockIdx.x * blockDim.x + threadIdx.x;
    int d    = idx >> 4;
    int lane = idx & 15;
    if (d >= NN) return;
    float4 b = reinterpret_cast<const float4*>(bias)[lane];
    float4 acc = reinterpret_cast<const float4*>(root)[(size_t)d * 16 + lane];
    acc.x += b.x; acc.y += b.y; acc.z += b.z; acc.w += b.w;
    int beg = offs[d * R];
    for (int r = 0; r < R; r++) {
        int key = d * R + r;
        int end = (key + 1 < NN * R) ? offs[key + 1] : E;
        if (end > beg) {
            float4 s = make_float4(0.f, 0.f, 0.f, 0.f);
            for (int e = beg; e < end; e++) {
                int sv = ssrc[e];
                float4 v = reinterpret_cast<const float4*>(W)[((size_t)r * NN + sv) * 16 + lane];
                s.x += v.x; s.y += v.y; s.z += v.z; s.w += v.w;
            }
            float inv = 1.0f / (float)(end - beg);
            acc.x += s.x * inv; acc.y += s.y * inv; acc.z += s.z * inv; acc.w += s.w * inv;
        }
        beg = end;
    }
    reinterpret_cast<float4*>(out)[(size_t)d * 16 + lane] = acc;
}

// ---------------- ATTITU fusion (warp per node) ----------------
__global__ void attitu_kernel(const float* __restrict__ ex1, const float* __restrict__ im1,
                              const float* __restrict__ w11, const float* __restrict__ b11,
                              const float* __restrict__ w12, const float* __restrict__ b12,
                              const float* __restrict__ w21, const float* __restrict__ b21,
                              const float* __restrict__ w22, const float* __restrict__ b22,
                              float* __restrict__ t_ex, float* __restrict__ t_im, int nnodes) {
    int g    = blockIdx.x * blockDim.x + threadIdx.x;
    int node = g >> 5;
    int lane = g & 31;
    if (node >= nnodes) return;
    const float* e1 = ex1 + (size_t)node * DD;
    const float* e2 = im1 + (size_t)node * DD;
    float a0 = e1[lane], a1 = e1[lane + 32];
    float c0 = e2[lane], c1 = e2[lane + 32];
    float p11 = a0 * w11[lane] + a1 * w11[lane + 32];
    float p12 = c0 * w12[lane] + c1 * w12[lane + 32];
    float p21 = a0 * w21[lane] + a1 * w21[lane + 32];
    float p22 = c0 * w22[lane] + c1 * w22[lane + 32];
    #pragma unroll
    for (int o = 16; o > 0; o >>= 1) {
        p11 += __shfl_xor_sync(0xFFFFFFFF, p11, o);
        p12 += __shfl_xor_sync(0xFFFFFFFF, p12, o);
        p21 += __shfl_xor_sync(0xFFFFFFFF, p21, o);
        p22 += __shfl_xor_sync(0xFFFFFFFF, p22, o);
    }
    float l0 = p11 + b11[0], l1 = p12 + b12[0];
    float m = fmaxf(l0, l1);
    float q0 = expf(l0 - m), q1 = expf(l1 - m);
    float inv = 1.0f / (q0 + q1);
    float s0 = q0 * inv, s1 = q1 * inv;
    t_ex[(size_t)node * DD + lane]      = s0 * a0 + s1 * c0;
    t_ex[(size_t)node * DD + lane + 32] = s0 * a1 + s1 * c1;
    float u0 = p21 + b21[0], u1 = p22 + b22[0];
    float m2 = fmaxf(u0, u1);
    float r0 = expf(u0 - m2), r1 = expf(u1 - m2);
    float inv2 = 1.0f / (r0 + r1);
    float t0 = r0 * inv2, t1 = r1 * inv2;
    t_im[(size_t)node * DD + lane]      = t0 * a0 + t1 * c0;
    t_im[(size_t)node * DD + lane + 32] = t0 * a1 + t1 * c1;
}

// ---------------- fused layer-2, bf16x3 m16n8k16 tensor cores ----------
// out = x1 + b2 + t@root2 + sum_r mean_r(t) @ W2[r]
__global__ __launch_bounds__(256)
void l2_fused_tc(const float* __restrict__ t, const int* __restrict__ ssrc,
                 const int* __restrict__ offs,
                 const float* __restrict__ W2, const float* __restrict__ root2,
                 const float* __restrict__ b2, const float* __restrict__ x1,
                 float* __restrict__ out, int R, int E) {
    extern __shared__ float sm[];
    float*    As  = sm;                                   // 128*68 fp32
    unsigned* Bph = reinterpret_cast<unsigned*>(sm + 128 * AS_STR);   // 32*72
    unsigned* Bpl = Bph + 32 * BP_STR;                    // 32*72
    int tid  = threadIdx.x;
    int lane = tid & 31, warp = tid >> 5;
    int lr = lane >> 2;
    int lc = lane & 3;
    int row0 = blockIdx.x * 128;
    int rip = tid >> 4;
    int c4  = tid & 15;

    float acc[8][4];
    #pragma unroll
    for (int i = 0; i < 8; i++)
        #pragma unroll
        for (int j = 0; j < 4; j++) acc[i][j] = 0.0f;

    for (int r = 0; r <= R; r++) {
        const float* B = (r < R) ? (W2 + (size_t)r * 4096) : root2;
        load_B_pack(B, Bph, Bpl, tid);
        #pragma unroll
        for (int p = 0; p < 8; p++) {
            int arow = p * 16 + rip;
            int d_g  = row0 + arow;
            float4 s = make_float4(0.f, 0.f, 0.f, 0.f);
            if (d_g < NN) {
                if (r < R) {
                    int key = d_g * R + r;
                    int beg = offs[key];
                    int end = (key + 1 < NN * R) ? offs[key + 1] : E;
                    for (int e = beg; e < end; e++) {
                        float4 v = reinterpret_cast<const float4*>(t)[(size_t)ssrc[e] * 16 + c4];
                        s.x += v.x; s.y += v.y; s.z += v.z; s.w += v.w;
                    }
                    if (end > beg) {
                        float iv = 1.0f / (float)(end - beg);
                        s.x *= iv; s.y *= iv; s.z *= iv; s.w *= iv;
                    }
                } else {
                    s = reinterpret_cast<const float4*>(t)[(size_t)d_g * 16 + c4];
                }
            }
            *reinterpret_cast<float4*>(&As[arow * AS_STR + c4 * 4]) = s;
        }
        __syncthreads();
        mma_stage_bf16(As, Bph, Bpl, acc, warp, lr, lc);
        __syncthreads();
    }
    int gr0 = row0 + warp * 16 + lr;
    int gr1 = gr0 + 8;
    #pragma unroll
    for (int n0 = 0; n0 < 8; n0++) {
        int c = n0 * 8 + 2 * lc;
        if (gr0 < NN) {
            out[(size_t)gr0 * 64 + c]     = acc[n0][0] + b2[c]     + x1[(size_t)gr0 * 64 + c];
            out[(size_t)gr0 * 64 + c + 1] = acc[n0][1] + b2[c + 1] + x1[(size_t)gr0 * 64 + c + 1];
        }
        if (gr1 < NN) {
            out[(size_t)gr1 * 64 + c]     = acc[n0][2] + b2[c]     + x1[(size_t)gr1 * 64 + c];
            out[(size_t)gr1 * 64 + c + 1] = acc[n0][3] + b2[c + 1] + x1[(size_t)gr1 * 64 + c + 1];
        }
    }
}

// ---------------- fused MLP on bf16x3 tensor cores ----------------
// out = (leaky([ex|im] @ W1 + b1)) @ W2 + b2
__global__ __launch_bounds__(256)
void mlp_tc(const float* __restrict__ ex, const float* __restrict__ im,
            const float* __restrict__ W1, const float* __restrict__ b1,
            const float* __restrict__ W2, const float* __restrict__ b2,
            float* __restrict__ out) {
    extern __shared__ float sm[];
    float*    As  = sm;
    unsigned* Bph = reinterpret_cast<unsigned*>(sm + 128 * AS_STR);
    unsigned* Bpl = Bph + 32 * BP_STR;
    int tid  = threadIdx.x;
    int lane = tid & 31, warp = tid >> 5;
    int lr = lane >> 2, lc = lane & 3;
    int row0 = blockIdx.x * 128;
    int rip = tid >> 4, c4 = tid & 15;
    int gr0 = row0 + warp * 16 + lr;
    int gr1 = gr0 + 8;

    float acc[8][4];
    #pragma unroll
    for (int i = 0; i < 8; i++)
        #pragma unroll
        for (int j = 0; j < 4; j++) acc[i][j] = 0.0f;

    // stages 1,2: hidden = ex @ W1[0:64] + im @ W1[64:128]
    for (int stage = 0; stage < 2; stage++) {
        const float* A = stage ? im : ex;
        load_B_pack(W1 + (size_t)stage * 4096, Bph, Bpl, tid);
        #pragma unroll
        for (int p = 0; p < 8; p++) {
            int arow = p * 16 + rip;
            int d_g  = row0 + arow;
            float4 s = make_float4(0.f, 0.f, 0.f, 0.f);
            if (d_g < NN)
                s = reinterpret_cast<const float4*>(A)[(size_t)d_g * 16 + c4];
            *reinterpret_cast<float4*>(&As[arow * AS_STR + c4 * 4]) = s;
        }
        __syncthreads();
        mma_stage_bf16(As, Bph, Bpl, acc, warp, lr, lc);
        __syncthreads();
    }
    // bias + leaky on fragments; stage hidden into As (warp-private rows)
    #pragma unroll
    for (int n0 = 0; n0 < 8; n0++) {
        int c = n0 * 8 + 2 * lc;
        float b0 = b1[c], b1v = b1[c + 1];
        float v;
        int r0 = (warp * 16 + lr) * AS_STR;
        int r1 = r0 + 8 * AS_STR;
        v = acc[n0][0] + b0;  As[r0 + c]     = (v > 0.f) ? v : 0.01f * v;
        v = acc[n0][1] + b1v; As[r0 + c + 1] = (v > 0.f) ? v : 0.01f * v;
        v = acc[n0][2] + b0;  As[r1 + c]     = (v > 0.f) ? v : 0.01f * v;
        v = acc[n0][3] + b1v; As[r1 + c + 1] = (v > 0.f) ? v : 0.01f * v;
        acc[n0][0] = 0.f; acc[n0][1] = 0.f; acc[n0][2] = 0.f; acc[n0][3] = 0.f;
    }
    load_B_pack(W2, Bph, Bpl, tid);
    __syncthreads();
    // stage 3: out = hidden @ W2
    mma_stage_bf16(As, Bph, Bpl, acc, warp, lr, lc);
    #pragma unroll
    for (int n0 = 0; n0 < 8; n0++) {
        int c = n0 * 8 + 2 * lc;
        float b0 = b2[c], b1v = b2[c + 1];
        if (gr0 < NN) {
            out[(size_t)gr0 * 64 + c]     = acc[n0][0] + b0;
            out[(size_t)gr0 * 64 + c + 1] = acc[n0][1] + b1v;
        }
        if (gr1 < NN) {
            out[(size_t)gr1 * 64 + c]     = acc[n0][2] + b0;
            out[(size_t)gr1 * 64 + c + 1] = acc[n0][3] + b1v;
        }
    }
}

// ---------------- host ----------------
extern "C" void kernel_launch(void* const* d_in, const int* in_sizes, int n_in,
                              void* d_out, int out_size) {
    (void)in_sizes; (void)n_in; (void)out_size;
    const int*   ei_ex   = (const int*)d_in[0];
    const int*   et_ex   = (const int*)d_in[1];
    const int*   ei_im   = (const int*)d_in[2];
    const int*   et_im   = (const int*)d_in[3];
    const float* W1_ex   = (const float*)d_in[4];
    const float* root1_ex= (const float*)d_in[5];
    const float* b1_ex   = (const float*)d_in[6];
    const float* W1_im   = (const float*)d_in[7];
    const float* root1_im= (const float*)d_in[8];
    const float* b1_im   = (const float*)d_in[9];
    const float* W2_ex   = (const float*)d_in[10];
    const float* root2_ex= (const float*)d_in[11];
    const float* b2_ex   = (const float*)d_in[12];
    const float* W2_im   = (const float*)d_in[13];
    const float* root2_im= (const float*)d_in[14];
    const float* b2_im   = (const float*)d_in[15];
    const float* aw11 = (const float*)d_in[16]; const float* ab11 = (const float*)d_in[17];
    const float* aw12 = (const float*)d_in[18]; const float* ab12 = (const float*)d_in[19];
    const float* aw21 = (const float*)d_in[20]; const float* ab21 = (const float*)d_in[21];
    const float* aw22 = (const float*)d_in[22]; const float* ab22 = (const float*)d_in[23];
    const float* agg_W1 = (const float*)d_in[24]; const float* agg_b1 = (const float*)d_in[25];
    const float* agg_W2 = (const float*)d_in[26]; const float* agg_b2 = (const float*)d_in[27];
    float* out = (float*)d_out;

    const int* src_ex = ei_ex;
    const int* dst_ex = ei_ex + EEX;
    const int* src_im = ei_im;
    const int* dst_im = ei_im + EIM;

    void *p_cnt_ex, *p_cnt_im, *p_offs_ex, *p_offs_im, *p_cur_ex, *p_cur_im,
         *p_bs_ex, *p_bs_im, *p_ssrc_ex, *p_ssrc_im,
         *p_ex_x1, *p_im_x1, *p_t_ex, *p_t_im, *p_ex_sum, *p_im_sum;
    cudaGetSymbolAddress(&p_cnt_ex, g_cnt_ex);
    cudaGetSymbolAddress(&p_cnt_im, g_cnt_im);
    cudaGetSymbolAddress(&p_offs_ex, g_offs_ex);
    cudaGetSymbolAddress(&p_offs_im, g_offs_im);
    cudaGetSymbolAddress(&p_cur_ex, g_cur_ex);
    cudaGetSymbolAddress(&p_cur_im, g_cur_im);
    cudaGetSymbolAddress(&p_bs_ex, g_bs_ex);
    cudaGetSymbolAddress(&p_bs_im, g_bs_im);
    cudaGetSymbolAddress(&p_ssrc_ex, g_ssrc_ex);
    cudaGetSymbolAddress(&p_ssrc_im, g_ssrc_im);
    cudaGetSymbolAddress(&p_ex_x1, g_ex_x1);
    cudaGetSymbolAddress(&p_im_x1, g_im_x1);
    cudaGetSymbolAddress(&p_t_ex, g_t_ex);
    cudaGetSymbolAddress(&p_t_im, g_t_im);
    cudaGetSymbolAddress(&p_ex_sum, g_ex_sum);
    cudaGetSymbolAddress(&p_im_sum, g_im_sum);

    // zero counts (memsets don't count as kernel launches)
    cudaMemsetAsync(p_cnt_ex, 0, sizeof(int) * NRE);
    cudaMemsetAsync(p_cnt_im, 0, sizeof(int) * NRI);

    // kernel 1: counts (both edge sets)
    count_both<<<(EEX + EIM + 255) / 256, 256>>>(dst_ex, et_ex, dst_im, et_im,
                                                 (int*)p_cnt_ex, (int*)p_cnt_im);

    // kernel 2: level-1 scan (both arrays)
    scan1_both<<<NBE + NBI, 256>>>((const int*)p_cnt_ex, (int*)p_offs_ex, (int*)p_bs_ex,
                                   (const int*)p_cnt_im, (int*)p_offs_im, (int*)p_bs_im);

    // kernel 3: globalize offsets; writes offs AND cur
    scan_add2_both<<<NBE + NBI, 256>>>((const int*)p_bs_ex, (int*)p_offs_ex, (int*)p_cur_ex,
                                       (const int*)p_bs_im, (int*)p_offs_im, (int*)p_cur_im);

    // kernel 4 (profiled): counting sort (both edge sets)
    sort_both<<<(EEX + EIM + 255) / 256, 256>>>(src_ex, dst_ex, et_ex, src_im, dst_im, et_im,
                                                (int*)p_cur_ex, (int*)p_ssrc_ex,
                                                (int*)p_cur_im, (int*)p_ssrc_im);

    // kernels 5,6: layer-1 aggregation
    agg_l1<<<(NN * 16 + 255) / 256, 256>>>(W1_ex, (const int*)p_ssrc_ex, (const int*)p_offs_ex,
                                           root1_ex, b1_ex, (float*)p_ex_x1, REX, EEX);
    agg_l1<<<(NN * 16 + 255) / 256, 256>>>(W1_im, (const int*)p_ssrc_im, (const int*)p_offs_im,
                                           root1_im, b1_im, (float*)p_im_x1, RIM, EIM);

    // kernel 7: ATTITU fusion
    attitu_kernel<<<(NN * 32 + 255) / 256, 256>>>((const float*)p_ex_x1, (const float*)p_im_x1,
                                                  aw11, ab11, aw12, ab12, aw21, ab21, aw22, ab22,
                                                  (float*)p_t_ex, (float*)p_t_im, NN);

    const int tiles128 = (NN + 127) / 128;    // 782
    const int smem_tc = 128 * AS_STR * (int)sizeof(float) + 2 * 32 * BP_STR * (int)sizeof(unsigned);  // 53248 B

    // kernels 8,9: fused layer-2, bf16x3 tensor cores
    cudaFuncSetAttribute(l2_fused_tc, cudaFuncAttributeMaxDynamicSharedMemorySize, smem_tc);
    l2_fused_tc<<<tiles128, 256, smem_tc>>>((const float*)p_t_ex, (const int*)p_ssrc_ex,
                                            (const int*)p_offs_ex, W2_ex, root2_ex, b2_ex,
                                            (const float*)p_ex_x1, (float*)p_ex_sum, REX, EEX);
    l2_fused_tc<<<tiles128, 256, smem_tc>>>((const float*)p_t_im, (const int*)p_ssrc_im,
                                            (const int*)p_offs_im, W2_im, root2_im, b2_im,
                                            (const float*)p_im_x1, (float*)p_im_sum, RIM, EIM);

    // kernel 10: fused MLP on bf16x3 tensor cores -> writes d_out directly
    cudaFuncSetAttribute(mlp_tc, cudaFuncAttributeMaxDynamicSharedMemorySize, smem_tc);
    mlp_tc<<<tiles128, 256, smem_tc>>>((const float*)p_ex_sum, (const float*)p_im_sum,
                                       agg_W1, agg_b1, agg_W2, agg_b2, out);
}